// round 7
// baseline (speedup 1.0000x reference)
#include <cuda_runtime.h>
#include <mma.h>
#include <math.h>
#include <stdint.h>

using namespace nvcuda;

// Shapes fixed by the problem instance.
constexpr int kB  = 16;            // objects
constexpr int kP  = 4096;          // points per object
constexpr int kM  = 32;            // masks per object
constexpr int kD  = 768;           // feature dim
constexpr int kN  = kB * kM;       // 512 total masks

// Segsum tiling: CTA = (64 d-cols, object) -> grid 12x16 = 192 CTAs,
// 2 CTAs/SM (all resident). 8 warps: kg = w&1 (k-half), nw = w>>1 (16 cols).
constexpr int DC   = 64;
constexpr int NDCC = kD / DC;      // 12
constexpr int KT   = 64;
constexpr int NIT  = kP / KT;      // 64
constexpr int SEG_THREADS = 256;

// Segsum dynamic smem (4-stage pipeline):
constexpr int BST   = 68;                        // B row stride (floats)
constexpr int B_STG = KT * BST * 4;              // 17408 B per stage
constexpr int AST   = 68;                        // A row stride (floats)
constexpr int A_OFF = 4 * B_STG;                 // 69632
constexpr int A_STG = kM * AST * 4;              // 8704 B per stage
constexpr int SEG_SMEM = A_OFF + 4 * A_STG;      // 104448 B -> 2 CTAs/SM

// Scratch (device globals; no allocation allowed).
__device__ float g_afloat[kB * kM * kP];   // mask as fp32 {0,1}, [b][m][p]
__device__ float g_npts[kN];
__device__ float g_avg[kN * kD];
__device__ float g_logits[kN * kN];
__device__ float g_logitsT[kN * kN];
__device__ float g_tloss[kN];
__device__ float g_ploss[kN];

__device__ __forceinline__ void cpa16(uint32_t dst, const void* src) {
    asm volatile("cp.async.ca.shared.global [%0], [%1], 16;" :: "r"(dst), "l"(src));
}
#define CP_COMMIT() asm volatile("cp.async.commit_group;")
#define CP_WAIT(n)  asm volatile("cp.async.wait_group %0;" :: "n"(n))

// ---------------------------------------------------------------------------
__global__ void zero_kernel() { g_npts[threadIdx.x] = 0.f; }
__global__ void dummy_kernel() {}   // shifts segsum to 4th launch for ncu

// ---------------------------------------------------------------------------
// Pack: mask_pts [b][m][p] -> g_afloat (fp32 0/1) + npts (ballot popc, exact).
// ---------------------------------------------------------------------------
__global__ void pack_kernel(const float* __restrict__ mp) {
    const int b = blockIdx.y;
    const int p = blockIdx.x * blockDim.x + threadIdx.x;
    const int lane = threadIdx.x & 31;
    unsigned bm = 0;
#pragma unroll
    for (int m = 0; m < kM; ++m) {
        size_t idx = ((size_t)(b * kM + m)) * kP + p;
        float v = mp[idx];
        bool on = v > 0.5f;
        bm |= on ? (1u << m) : 0u;
        g_afloat[idx] = on ? 1.f : 0.f;
    }
    unsigned cmine = 0;
#pragma unroll
    for (int m = 0; m < kM; ++m) {
        unsigned bal = __ballot_sync(0xffffffffu, (bm >> m) & 1u);
        if (lane == m) cmine = __popc(bal);
    }
    atomicAdd(&g_npts[b * kM + lane], (float)cmine);
}

// ---------------------------------------------------------------------------
// Segmented sum via tf32 wmma; avg fused into epilogue.
// Per CTA (dc, b): out[32, 64] = mask[32, 4096] @ net_out_b[4096, 64]
// 4-stage cp.async pipeline; A tile is pure cp.async from g_afloat.
// ---------------------------------------------------------------------------
__global__ __launch_bounds__(SEG_THREADS) void segsum_mma(const float* __restrict__ net_out) {
    extern __shared__ char smc[];
    float* smB = (float*)smc;
    float* smA = (float*)(smc + A_OFF);
    const uint32_t base = (uint32_t)__cvta_generic_to_shared(smc);
    const int tid = threadIdx.x, w = tid >> 5;
    const int kg = w & 1, nw = w >> 1;
    const int dc = blockIdx.x, b = blockIdx.y;
    const float4* __restrict__ net4 =
        (const float4*)net_out + (size_t)b * kP * (kD / 4) + dc * (DC / 4);
    const float* __restrict__ afl = g_afloat + (size_t)b * kM * kP;

    auto ISSUE = [&](int it) {
        const int stage = it & 3;
        const int p0 = it * KT;
        const uint32_t bb = base + stage * B_STG;
        const uint32_t ab = base + A_OFF + stage * A_STG;
#pragma unroll
        for (int j = 0; j < 4; ++j) {                  // B: 64 rows x 16 chunks
            int c = tid + j * SEG_THREADS;
            int r = c >> 4, c16 = c & 15;
            cpa16(bb + (uint32_t)(r * BST + c16 * 4) * 4,
                  net4 + (size_t)(p0 + r) * (kD / 4) + c16);
        }
#pragma unroll
        for (int j = 0; j < 2; ++j) {                  // A: 32 rows x 16 chunks
            int c = tid + j * SEG_THREADS;
            int r = c >> 4, c16 = c & 15;
            cpa16(ab + (uint32_t)(r * AST + c16 * 4) * 4,
                  afl + (size_t)r * kP + p0 + c16 * 4);
        }
        CP_COMMIT();
    };

    wmma::fragment<wmma::accumulator, 16, 16, 8, float> acc0, acc1;
    wmma::fill_fragment(acc0, 0.f);
    wmma::fill_fragment(acc1, 0.f);

    ISSUE(0); ISSUE(1); ISSUE(2);
    for (int it = 0; it < NIT; ++it) {
        const int stage = it & 3;
        const int rem = NIT - 1 - it;
        if (rem >= 2)      CP_WAIT(2);
        else if (rem == 1) CP_WAIT(1);
        else               CP_WAIT(0);
        __syncthreads();
        if (it + 3 < NIT) ISSUE(it + 3);

        const float* A = smA + stage * (A_STG / 4);
        const float* B = smB + stage * (B_STG / 4);
#pragma unroll
        for (int ks = 0; ks < 4; ++ks) {
            const int kk = kg * 32 + ks * 8;
            wmma::fragment<wmma::matrix_a, 16, 16, 8, wmma::precision::tf32, wmma::row_major> a0, a1;
            wmma::fragment<wmma::matrix_b, 16, 16, 8, wmma::precision::tf32, wmma::row_major> bf;
            wmma::load_matrix_sync(a0, A + kk, AST);
            wmma::load_matrix_sync(a1, A + 16 * AST + kk, AST);
            wmma::load_matrix_sync(bf, B + kk * BST + nw * 16, BST);
            // A is exact {0,1} in tf32; round only B.
#pragma unroll
            for (int i = 0; i < bf.num_elements; ++i)
                bf.x[i] = wmma::__float_to_tf32(bf.x[i]);
            wmma::mma_sync(acc0, a0, bf, acc0);
            wmma::mma_sync(acc1, a1, bf, acc1);
        }
    }

    // Reduce kg halves + fused avg. Reuse smB as staging: [2][32][64].
    __syncthreads();
    float* so = smB + kg * (kM * DC);
    wmma::store_matrix_sync(so + nw * 16, acc0, DC, wmma::mem_row_major);
    wmma::store_matrix_sync(so + 16 * DC + nw * 16, acc1, DC, wmma::mem_row_major);
    __syncthreads();
#pragma unroll
    for (int j = 0; j < 8; ++j) {
        int idx = tid + j * SEG_THREADS;               // 2048 outputs
        int m = idx >> 6, c = idx & 63;
        float v = smB[idx] + smB[kM * DC + idx];
        float inv = 1.f / (g_npts[b * kM + m] + 1e-12f);
        g_avg[(size_t)(b * kM + m) * kD + dc * DC + c] = v * inv;
    }
}

// ---------------------------------------------------------------------------
// logits = scale * emb @ avg^T  (512x512x768) via tf32 wmma.
// CTA = 32x32 tile, grid 16x16 = 256 CTAs, 128 threads (4 warps = quadrants),
// 4-stage cp.async. Writes logits AND logits^T (coalesced loss passes).
// ---------------------------------------------------------------------------
constexpr int LK = 32;
__global__ __launch_bounds__(128) void logits_mma(const float* __restrict__ emb,
                                                  const float* __restrict__ lscale) {
    __shared__ __align__(16) float sA[4][32][36];
    __shared__ __align__(16) float sB[4][32][36];
    const int tid = threadIdx.x, w = tid >> 5;
    const int mw = w >> 1, nw = w & 1;
    const int bi = blockIdx.y, bj = blockIdx.x;
    const uint32_t aA = (uint32_t)__cvta_generic_to_shared(&sA[0][0][0]);
    const uint32_t aB = (uint32_t)__cvta_generic_to_shared(&sB[0][0][0]);

    auto ISSUE = [&](int it) {
        int st = it & 3, k0 = it * LK;
#pragma unroll
        for (int j = 0; j < 2; ++j) {           // 256 chunks each matrix
            int e = tid + j * 128;
            int r = e >> 3, c4 = e & 7;
            cpa16(aA + (uint32_t)(st * 32 * 36 + r * 36 + c4 * 4) * 4,
                  emb + (size_t)(bi * 32 + r) * kD + k0 + c4 * 4);
            cpa16(aB + (uint32_t)(st * 32 * 36 + r * 36 + c4 * 4) * 4,
                  g_avg + (size_t)(bj * 32 + r) * kD + k0 + c4 * 4);
        }
        CP_COMMIT();
    };

    wmma::fragment<wmma::accumulator, 16, 16, 8, float> acc;
    wmma::fill_fragment(acc, 0.f);

    ISSUE(0); ISSUE(1); ISSUE(2);
    const int KIT = kD / LK;                    // 24
    for (int it = 0; it < KIT; ++it) {
        int st = it & 3;
        const int rem = KIT - 1 - it;
        if (rem >= 2)      CP_WAIT(2);
        else if (rem == 1) CP_WAIT(1);
        else               CP_WAIT(0);
        __syncthreads();
        if (it + 3 < KIT) ISSUE(it + 3);
#pragma unroll
        for (int ks = 0; ks < 4; ++ks) {
            wmma::fragment<wmma::matrix_a, 16, 16, 8, wmma::precision::tf32, wmma::row_major> af;
            wmma::fragment<wmma::matrix_b, 16, 16, 8, wmma::precision::tf32, wmma::col_major> bf;
            wmma::load_matrix_sync(af, &sA[st][mw * 16][ks * 8], 36);
            wmma::load_matrix_sync(bf, &sB[st][nw * 16][ks * 8], 36);
#pragma unroll
            for (int i = 0; i < af.num_elements; ++i)
                af.x[i] = wmma::__float_to_tf32(af.x[i]);
#pragma unroll
            for (int i = 0; i < bf.num_elements; ++i)
                bf.x[i] = wmma::__float_to_tf32(bf.x[i]);
            wmma::mma_sync(acc, af, bf, acc);
        }
    }

    __syncthreads();
    float* so = &sA[0][0][0];                   // 32 x 36 staging (reuse)
    wmma::store_matrix_sync(so + (mw * 16) * 36 + nw * 16, acc, 36, wmma::mem_row_major);
    __syncthreads();
    const float scale = expf(lscale[0]);
#pragma unroll
    for (int j = 0; j < 2; ++j) {               // logits rows (coalesced)
        int e = tid + j * 128;                  // 256 float4 chunks
        int r = e >> 3, c4 = e & 7;
        float4 v = *(float4*)(so + r * 36 + c4 * 4);
        v.x *= scale; v.y *= scale; v.z *= scale; v.w *= scale;
        *(float4*)&g_logits[(size_t)(bi * 32 + r) * kN + bj * 32 + c4 * 4] = v;
    }
#pragma unroll
    for (int j = 0; j < 2; ++j) {               // logits^T rows (coalesced)
        int e = tid + j * 128;
        int c = e >> 3, i4 = e & 7;             // col of logits, row-quad of i
        float4 v = make_float4(so[(i4 * 4 + 0) * 36 + c] * scale,
                               so[(i4 * 4 + 1) * 36 + c] * scale,
                               so[(i4 * 4 + 2) * 36 + c] * scale,
                               so[(i4 * 4 + 3) * 36 + c] * scale);
        *(float4*)&g_logitsT[(size_t)(bj * 32 + c) * kN + bi * 32 + i4 * 4] = v;
    }
}

// ---------------------------------------------------------------------------
// Loss: blocks 0..511 rows of logits (texts); 512..1023 rows of logits^T (pts).
// ---------------------------------------------------------------------------
__global__ __launch_bounds__(128) void loss_kernel() {
    const int bid = blockIdx.x;
    const int i = bid & (kN - 1);
    const float* __restrict__ row = (bid < kN ? g_logits : g_logitsT) + (size_t)i * kN;
    const int t = threadIdx.x;
    __shared__ float sr[128];

    float rmax = -3.0e38f;
#pragma unroll
    for (int j = t; j < kN; j += 128) rmax = fmaxf(rmax, row[j]);
    sr[t] = rmax;
    __syncthreads();
    for (int w = 64; w > 0; w >>= 1) {
        if (t < w) sr[t] = fmaxf(sr[t], sr[t + w]);
        __syncthreads();
    }
    rmax = sr[0];
    __syncthreads();

    float rs = 0.f;
#pragma unroll
    for (int j = t; j < kN; j += 128) rs += expf(row[j] - rmax);
    sr[t] = rs;
    __syncthreads();
    for (int w = 64; w > 0; w >>= 1) {
        if (t < w) sr[t] += sr[t + w];
        __syncthreads();
    }
    if (t == 0) {
        bool valid = g_npts[i] > 0.f;
        float lse = rmax + logf(sr[0]) - row[i];
        (bid < kN ? g_tloss : g_ploss)[i] = valid ? lse : 0.f;
    }
}

// ---------------------------------------------------------------------------
// Final: nonzero-mean of both loss vectors, averaged.
// ---------------------------------------------------------------------------
__global__ void final_kernel(float* __restrict__ out) {
    const int t = threadIdx.x;   // 512 threads
    __shared__ float s_ts[512], s_tc[512], s_ps[512], s_pc[512];
    float tl = g_tloss[t], pl = g_ploss[t];
    s_ts[t] = (tl > 0.f) ? tl : 0.f;
    s_tc[t] = (tl > 0.f) ? 1.f : 0.f;
    s_ps[t] = (pl > 0.f) ? pl : 0.f;
    s_pc[t] = (pl > 0.f) ? 1.f : 0.f;
    __syncthreads();
    for (int w = 256; w > 0; w >>= 1) {
        if (t < w) {
            s_ts[t] += s_ts[t + w]; s_tc[t] += s_tc[t + w];
            s_ps[t] += s_ps[t + w]; s_pc[t] += s_pc[t + w];
        }
        __syncthreads();
    }
    if (t == 0) {
        float tm = (s_tc[0] > 0.f) ? s_ts[0] / s_tc[0] : 0.f;
        float pm = (s_pc[0] > 0.f) ? s_ps[0] / s_pc[0] : 0.f;
        out[0] = 0.5f * (tm + pm);
    }
}

// ---------------------------------------------------------------------------
// Launch. Inputs: net_out, pt_offset, mask_embs, mask_pts, logit_scale.
// dummy_kernel makes segsum the 4th launch (ncu captures the 4th).
// ---------------------------------------------------------------------------
extern "C" void kernel_launch(void* const* d_in, const int* in_sizes, int n_in,
                              void* d_out, int out_size) {
    (void)in_sizes; (void)n_in; (void)out_size;
    const float* net_out   = (const float*)d_in[0];
    const float* mask_embs = (const float*)d_in[2];
    const float* mask_pts  = (const float*)d_in[3];
    const float* lscale    = (const float*)d_in[4];

    cudaFuncSetAttribute(segsum_mma,
                         cudaFuncAttributeMaxDynamicSharedMemorySize, SEG_SMEM);

    zero_kernel<<<1, kN>>>();
    pack_kernel<<<dim3(kP / 256, kB), 256>>>(mask_pts);
    dummy_kernel<<<1, 1>>>();
    segsum_mma<<<dim3(NDCC, kB), SEG_THREADS, SEG_SMEM>>>(net_out);
    logits_mma<<<dim3(16, 16), 128>>>(mask_embs, lscale);
    loss_kernel<<<2 * kN, 128>>>();
    final_kernel<<<1, kN>>>((float*)d_out);
}

// round 9
// speedup vs baseline: 1.1392x; 1.1392x over previous
#include <cuda_runtime.h>
#include <mma.h>
#include <math.h>
#include <stdint.h>

using namespace nvcuda;

// Shapes fixed by the problem instance.
constexpr int kB  = 16;            // objects
constexpr int kP  = 4096;          // points per object
constexpr int kM  = 32;            // masks per object
constexpr int kD  = 768;           // feature dim
constexpr int kN  = kB * kM;       // 512 total masks

// Segsum tiling: CTA = (64 d-cols, object) -> grid 12x16 = 192 CTAs.
// 8 warps: kg = w&1 (k-half of 64-pt tile), nw = w>>1 (16-col group).
constexpr int DC   = 64;
constexpr int NDCC = kD / DC;      // 12
constexpr int KT   = 64;
constexpr int NIT  = kP / KT;      // 64
constexpr int SEG_THREADS = 256;

// Segsum smem: 2 stages of (B[64][68] + A[32][68]) floats.
constexpr int BST   = 68;                        // B row stride (floats)
constexpr int B_STG = KT * BST * 4;              // 17408 B per stage
constexpr int AST   = 68;                        // A row stride (floats)
constexpr int A_OFF = 2 * B_STG;                 // 34816
constexpr int A_STG = kM * AST * 4;              // 8704 B per stage
constexpr int SEG_SMEM = A_OFF + 2 * A_STG;      // 52224 B -> 2 CTAs/SM

// Scratch (device globals; no allocation allowed).
__device__ float g_npts[kN];
__device__ float g_avg[kN * kD];
__device__ float g_logits[kN * kN];
__device__ float g_logitsT[kN * kN];
__device__ float g_tloss[kN];
__device__ float g_ploss[kN];

__device__ __forceinline__ void cpa16(uint32_t dst, const void* src) {
    asm volatile("cp.async.ca.shared.global [%0], [%1], 16;" :: "r"(dst), "l"(src));
}
#define CP_COMMIT() asm volatile("cp.async.commit_group;")
#define CP_WAIT(n)  asm volatile("cp.async.wait_group %0;" :: "n"(n))

// ---------------------------------------------------------------------------
__global__ void dummy_kernel() {}   // keeps segsum as the 4th launch for ncu

// ---------------------------------------------------------------------------
// npts[b*M+m] = sum_p mask_pts[b][m][p]  (one block per mask row)
// ---------------------------------------------------------------------------
__global__ void npts_kernel(const float* __restrict__ mp) {
    const int id = blockIdx.x;          // b*M + m
    const int t = threadIdx.x;
    float s = 0.f;
    for (int p = t; p < kP; p += 256)
        s += mp[(size_t)id * kP + p];
    __shared__ float sm[256];
    sm[t] = s;
    __syncthreads();
    for (int w = 128; w > 0; w >>= 1) {
        if (t < w) sm[t] += sm[t + w];
        __syncthreads();
    }
    if (t == 0) g_npts[id] = sm[0];
}

// ---------------------------------------------------------------------------
// Segmented sum via tf32 wmma; avg fused into epilogue.
// Per CTA (dc, b): out[32, 64] = mask[32, 4096] @ net_out_b[4096, 64]
// A streams DIRECTLY from mask_pts (already fp32 {0,1}, [b][m][p]).
// Copies use LDG.128 -> STS.128 (512B/warp-inst) to dodge the cp.async
// 16B/op LSU-issue floor (~1.4TB/s) measured in R7. Two register prefetch
// sets + 2-stage smem double buffer.
// ---------------------------------------------------------------------------
__global__ __launch_bounds__(SEG_THREADS) void segsum_mma(
        const float* __restrict__ net_out, const float* __restrict__ mask) {
    extern __shared__ char smc[];
    float* smB = (float*)smc;                     // 2 stages [64][68]
    float* smA = (float*)(smc + A_OFF);           // 2 stages [32][68]
    const int tid = threadIdx.x, w = tid >> 5;
    const int kg = w & 1, nw = w >> 1;
    const int dc = blockIdx.x, b = blockIdx.y;
    const float4* __restrict__ net4 =
        (const float4*)net_out + (size_t)b * kP * (kD / 4) + dc * (DC / 4);
    const float* __restrict__ mkb = mask + (size_t)b * kM * kP;

    // Per-thread copy mapping (B rows and A rows): r = c>>4, c16 = c&15.
    const int br0 = tid >> 4;
    const int bc = tid & 15;
    const int ar0 = tid >> 4, ar1 = (tid + 256) >> 4;

    float4 vb0[4], vb1[4], va0[2], va1[2];
    auto LDG = [&](int it, float4* vb, float4* va) {
        const int p0 = it * KT;
#pragma unroll
        for (int j = 0; j < 4; ++j)
            vb[j] = net4[(size_t)(p0 + br0 + j * 16) * (kD / 4) + bc];
        va[0] = *(const float4*)&mkb[(size_t)ar0 * kP + p0 + bc * 4];
        va[1] = *(const float4*)&mkb[(size_t)ar1 * kP + p0 + bc * 4];
    };
    auto STS = [&](int stage, const float4* vb, const float4* va) {
        float* Bd = smB + stage * (B_STG / 4);
        float* Ad = smA + stage * (A_STG / 4);
#pragma unroll
        for (int j = 0; j < 4; ++j)
            *(float4*)&Bd[(br0 + j * 16) * BST + bc * 4] = vb[j];
        *(float4*)&Ad[ar0 * AST + bc * 4] = va[0];
        *(float4*)&Ad[ar1 * AST + bc * 4] = va[1];
    };

    wmma::fragment<wmma::accumulator, 16, 16, 8, float> acc0, acc1;
    wmma::fill_fragment(acc0, 0.f);
    wmma::fill_fragment(acc1, 0.f);

    LDG(0, vb0, va0);
    LDG(1, vb1, va1);
    STS(0, vb0, va0);
    __syncthreads();

    for (int it = 0; it < NIT; ++it) {
        const int stage = it & 1;
        // Prefetch tile it+2 into the register set whose data is already in smem.
        if (it + 2 < NIT) {
            if (stage == 0) LDG(it + 2, vb0, va0);
            else            LDG(it + 2, vb1, va1);
        }
        // Stage tile it+1 into the other smem buffer while computing tile it.
        if (it + 1 < NIT) {
            if (stage == 0) STS(1, vb1, va1);
            else            STS(0, vb0, va0);
        }

        const float* A = smA + stage * (A_STG / 4);
        const float* B = smB + stage * (B_STG / 4);
#pragma unroll
        for (int ks = 0; ks < 4; ++ks) {
            const int kk = kg * 32 + ks * 8;
            wmma::fragment<wmma::matrix_a, 16, 16, 8, wmma::precision::tf32, wmma::row_major> a0, a1;
            wmma::fragment<wmma::matrix_b, 16, 16, 8, wmma::precision::tf32, wmma::row_major> bf;
            wmma::load_matrix_sync(a0, A + kk, AST);
            wmma::load_matrix_sync(a1, A + 16 * AST + kk, AST);
            wmma::load_matrix_sync(bf, B + kk * BST + nw * 16, BST);
            // A is exact {0,1} in tf32; round only B.
#pragma unroll
            for (int i = 0; i < bf.num_elements; ++i)
                bf.x[i] = wmma::__float_to_tf32(bf.x[i]);
            wmma::mma_sync(acc0, a0, bf, acc0);
            wmma::mma_sync(acc1, a1, bf, acc1);
        }
        __syncthreads();
    }

    // Reduce kg halves + fused avg. Reuse smB as staging: [2][32][64].
    float* so = smB + kg * (kM * DC);
    wmma::store_matrix_sync(so + nw * 16, acc0, DC, wmma::mem_row_major);
    wmma::store_matrix_sync(so + 16 * DC + nw * 16, acc1, DC, wmma::mem_row_major);
    __syncthreads();
#pragma unroll
    for (int j = 0; j < 8; ++j) {
        int idx = tid + j * SEG_THREADS;               // 2048 outputs
        int m = idx >> 6, c = idx & 63;
        float v = smB[idx] + smB[kM * DC + idx];
        float inv = 1.f / (g_npts[b * kM + m] + 1e-12f);
        g_avg[(size_t)(b * kM + m) * kD + dc * DC + c] = v * inv;
    }
}

// ---------------------------------------------------------------------------
// logits = scale * emb @ avg^T  (512x512x768) via tf32 wmma.
// CTA = 32x32 tile, grid 16x16 = 256 CTAs, 128 threads, 4-stage cp.async.
// Writes logits AND logits^T (coalesced loss passes).
// ---------------------------------------------------------------------------
constexpr int LK = 32;
__global__ __launch_bounds__(128) void logits_mma(const float* __restrict__ emb,
                                                  const float* __restrict__ lscale) {
    __shared__ __align__(16) float sA[4][32][36];
    __shared__ __align__(16) float sB[4][32][36];
    const int tid = threadIdx.x, w = tid >> 5;
    const int mw = w >> 1, nw = w & 1;
    const int bi = blockIdx.y, bj = blockIdx.x;
    const uint32_t aA = (uint32_t)__cvta_generic_to_shared(&sA[0][0][0]);
    const uint32_t aB = (uint32_t)__cvta_generic_to_shared(&sB[0][0][0]);

    auto ISSUE = [&](int it) {
        int st = it & 3, k0 = it * LK;
#pragma unroll
        for (int j = 0; j < 2; ++j) {           // 256 chunks each matrix
            int e = tid + j * 128;
            int r = e >> 3, c4 = e & 7;
            cpa16(aA + (uint32_t)(st * 32 * 36 + r * 36 + c4 * 4) * 4,
                  emb + (size_t)(bi * 32 + r) * kD + k0 + c4 * 4);
            cpa16(aB + (uint32_t)(st * 32 * 36 + r * 36 + c4 * 4) * 4,
                  g_avg + (size_t)(bj * 32 + r) * kD + k0 + c4 * 4);
        }
        CP_COMMIT();
    };

    wmma::fragment<wmma::accumulator, 16, 16, 8, float> acc;
    wmma::fill_fragment(acc, 0.f);

    ISSUE(0); ISSUE(1); ISSUE(2);
    const int KIT = kD / LK;                    // 24
    for (int it = 0; it < KIT; ++it) {
        int st = it & 3;
        const int rem = KIT - 1 - it;
        if (rem >= 2)      CP_WAIT(2);
        else if (rem == 1) CP_WAIT(1);
        else               CP_WAIT(0);
        __syncthreads();
        if (it + 3 < KIT) ISSUE(it + 3);
#pragma unroll
        for (int ks = 0; ks < 4; ++ks) {
            wmma::fragment<wmma::matrix_a, 16, 16, 8, wmma::precision::tf32, wmma::row_major> af;
            wmma::fragment<wmma::matrix_b, 16, 16, 8, wmma::precision::tf32, wmma::col_major> bf;
            wmma::load_matrix_sync(af, &sA[st][mw * 16][ks * 8], 36);
            wmma::load_matrix_sync(bf, &sB[st][nw * 16][ks * 8], 36);
#pragma unroll
            for (int i = 0; i < af.num_elements; ++i)
                af.x[i] = wmma::__float_to_tf32(af.x[i]);
#pragma unroll
            for (int i = 0; i < bf.num_elements; ++i)
                bf.x[i] = wmma::__float_to_tf32(bf.x[i]);
            wmma::mma_sync(acc, af, bf, acc);
        }
        __syncthreads();
    }

    float* so = &sA[0][0][0];                   // 32 x 36 staging (reuse)
    wmma::store_matrix_sync(so + (mw * 16) * 36 + nw * 16, acc, 36, wmma::mem_row_major);
    __syncthreads();
    const float scale = expf(lscale[0]);
#pragma unroll
    for (int j = 0; j < 2; ++j) {               // logits rows (coalesced)
        int e = tid + j * 128;                  // 256 float4 chunks
        int r = e >> 3, c4 = e & 7;
        float4 v = *(float4*)(so + r * 36 + c4 * 4);
        v.x *= scale; v.y *= scale; v.z *= scale; v.w *= scale;
        *(float4*)&g_logits[(size_t)(bi * 32 + r) * kN + bj * 32 + c4 * 4] = v;
    }
#pragma unroll
    for (int j = 0; j < 2; ++j) {               // logits^T rows (coalesced)
        int e = tid + j * 128;
        int c = e >> 3, i4 = e & 7;             // col of logits, row-quad of i
        float4 v = make_float4(so[(i4 * 4 + 0) * 36 + c] * scale,
                               so[(i4 * 4 + 1) * 36 + c] * scale,
                               so[(i4 * 4 + 2) * 36 + c] * scale,
                               so[(i4 * 4 + 3) * 36 + c] * scale);
        *(float4*)&g_logitsT[(size_t)(bj * 32 + c) * kN + bi * 32 + i4 * 4] = v;
    }
}

// ---------------------------------------------------------------------------
// Loss: blocks 0..511 rows of logits (texts); 512..1023 rows of logits^T (pts).
// ---------------------------------------------------------------------------
__global__ __launch_bounds__(128) void loss_kernel() {
    const int bid = blockIdx.x;
    const int i = bid & (kN - 1);
    const float* __restrict__ row = (bid < kN ? g_logits : g_logitsT) + (size_t)i * kN;
    const int t = threadIdx.x;
    __shared__ float sr[128];

    float rmax = -3.0e38f;
#pragma unroll
    for (int j = t; j < kN; j += 128) rmax = fmaxf(rmax, row[j]);
    sr[t] = rmax;
    __syncthreads();
    for (int w = 64; w > 0; w >>= 1) {
        if (t < w) sr[t] = fmaxf(sr[t], sr[t + w]);
        __syncthreads();
    }
    rmax = sr[0];
    __syncthreads();

    float rs = 0.f;
#pragma unroll
    for (int j = t; j < kN; j += 128) rs += expf(row[j] - rmax);
    sr[t] = rs;
    __syncthreads();
    for (int w = 64; w > 0; w >>= 1) {
        if (t < w) sr[t] += sr[t + w];
        __syncthreads();
    }
    if (t == 0) {
        bool valid = g_npts[i] > 0.f;
        float lse = rmax + logf(sr[0]) - row[i];
        (bid < kN ? g_tloss : g_ploss)[i] = valid ? lse : 0.f;
    }
}

// ---------------------------------------------------------------------------
// Final: nonzero-mean of both loss vectors, averaged.
// ---------------------------------------------------------------------------
__global__ void final_kernel(float* __restrict__ out) {
    const int t = threadIdx.x;   // 512 threads
    __shared__ float s_ts[512], s_tc[512], s_ps[512], s_pc[512];
    float tl = g_tloss[t], pl = g_ploss[t];
    s_ts[t] = (tl > 0.f) ? tl : 0.f;
    s_tc[t] = (tl > 0.f) ? 1.f : 0.f;
    s_ps[t] = (pl > 0.f) ? pl : 0.f;
    s_pc[t] = (pl > 0.f) ? 1.f : 0.f;
    __syncthreads();
    for (int w = 256; w > 0; w >>= 1) {
        if (t < w) {
            s_ts[t] += s_ts[t + w]; s_tc[t] += s_tc[t + w];
            s_ps[t] += s_ps[t + w]; s_pc[t] += s_pc[t + w];
        }
        __syncthreads();
    }
    if (t == 0) {
        float tm = (s_tc[0] > 0.f) ? s_ts[0] / s_tc[0] : 0.f;
        float pm = (s_pc[0] > 0.f) ? s_ps[0] / s_pc[0] : 0.f;
        out[0] = 0.5f * (tm + pm);
    }
}

// ---------------------------------------------------------------------------
// Launch. Inputs: net_out, pt_offset, mask_embs, mask_pts, logit_scale.
// npts + 2 dummies keep segsum as the 4th launch (ncu captures the 4th).
// ---------------------------------------------------------------------------
extern "C" void kernel_launch(void* const* d_in, const int* in_sizes, int n_in,
                              void* d_out, int out_size) {
    (void)in_sizes; (void)n_in; (void)out_size;
    const float* net_out   = (const float*)d_in[0];
    const float* mask_embs = (const float*)d_in[2];
    const float* mask_pts  = (const float*)d_in[3];
    const float* lscale    = (const float*)d_in[4];

    cudaFuncSetAttribute(segsum_mma,
                         cudaFuncAttributeMaxDynamicSharedMemorySize, SEG_SMEM);

    npts_kernel<<<kN, 256>>>(mask_pts);
    dummy_kernel<<<1, 1>>>();
    dummy_kernel<<<1, 1>>>();
    segsum_mma<<<dim3(NDCC, kB), SEG_THREADS, SEG_SMEM>>>(net_out, mask_pts);
    logits_mma<<<dim3(16, 16), 128>>>(mask_embs, lscale);
    loss_kernel<<<2 * kN, 128>>>();
    final_kernel<<<1, kN>>>((float*)d_out);
}

// round 12
// speedup vs baseline: 1.2347x; 1.0838x over previous
#include <cuda_runtime.h>
#include <mma.h>
#include <math.h>
#include <stdint.h>

using namespace nvcuda;

// Shapes fixed by the problem instance.
constexpr int kB  = 16;            // objects
constexpr int kP  = 4096;          // points per object
constexpr int kM  = 32;            // masks per object
constexpr int kD  = 768;           // feature dim
constexpr int kN  = kB * kM;       // 512 total masks

// Segsum tiling: CTA = (64 d-cols, object, k-half) -> grid 12x16x2 = 384 CTAs
// (2 resident CTAs/SM everywhere). 8 warps: kg = w&1, nw = w>>1.
constexpr int DC   = 64;
constexpr int NDCC = kD / DC;      // 12
constexpr int KT   = 64;
constexpr int KSP  = 2;            // K-split across CTAs
constexpr int NITK = kP / KT / KSP;// 32 iters per CTA
constexpr int SEG_THREADS = 256;

// Segsum smem: 2 stages of (B[64][68] + A[32][68]) floats.
constexpr int BST   = 68;                        // B row stride (floats)
constexpr int B_STG = KT * BST * 4;              // 17408 B per stage
constexpr int AST   = 68;                        // A row stride (floats)
constexpr int A_OFF = 2 * B_STG;                 // 34816
constexpr int A_STG = kM * AST * 4;              // 8704 B per stage
constexpr int SEG_SMEM = A_OFF + 2 * A_STG;      // 52224 B -> 2 CTAs/SM

// Scratch (device globals; no allocation allowed).
__device__ float g_npts[kN];
__device__ float g_part[KSP][kN * kD];     // k-split partial sums
__device__ float g_avg[kN * kD];
__device__ float g_logits[kN * kN];
__device__ float g_logitsT[kN * kN];
__device__ float g_tloss[kN];
__device__ float g_ploss[kN];

__device__ __forceinline__ void cpa16(uint32_t dst, const void* src) {
    asm volatile("cp.async.ca.shared.global [%0], [%1], 16;" :: "r"(dst), "l"(src));
}
#define CP_COMMIT() asm volatile("cp.async.commit_group;")
#define CP_WAIT(n)  asm volatile("cp.async.wait_group %0;" :: "n"(n))

// ---------------------------------------------------------------------------
__global__ void dummy_kernel() {}   // keeps segsum as the 4th launch for ncu

// ---------------------------------------------------------------------------
// npts[b*M+m] = sum_p mask_pts[b][m][p]  (one block per mask row)
// ---------------------------------------------------------------------------
__global__ void npts_kernel(const float* __restrict__ mp) {
    const int id = blockIdx.x;          // b*M + m
    const int t = threadIdx.x;
    float s = 0.f;
    for (int p = t; p < kP; p += 256)
        s += mp[(size_t)id * kP + p];
    __shared__ float sm[256];
    sm[t] = s;
    __syncthreads();
    for (int w = 128; w > 0; w >>= 1) {
        if (t < w) sm[t] += sm[t + w];
        __syncthreads();
    }
    if (t == 0) g_npts[id] = sm[0];
}

// ---------------------------------------------------------------------------
// Segmented sum via tf32 wmma (K-split partials).
// Per CTA (dc, b, ksp): part[32, 64] = mask[32, 2048-slice] @ B[slice, 64]
// A streams DIRECTLY from mask_pts (already fp32 {0,1} — exact in tf32, no
// rounding needed). B gets __float_to_tf32 RN rounding: R11 measured that
// dropping it (HW RZ truncation) biases the K=4096 accumulation to 1e-3.
// LDG.128 -> STS.128 copies (dodges the cp.async 16B/op issue floor).
// ---------------------------------------------------------------------------
__global__ __launch_bounds__(SEG_THREADS) void segsum_mma(
        const float* __restrict__ net_out, const float* __restrict__ mask) {
    extern __shared__ char smc[];
    float* smB = (float*)smc;                     // 2 stages [64][68]
    float* smA = (float*)(smc + A_OFF);           // 2 stages [32][68]
    const int tid = threadIdx.x, w = tid >> 5;
    const int kg = w & 1, nw = w >> 1;
    const int dc = blockIdx.x, b = blockIdx.y, ksp = blockIdx.z;
    const int pbase = ksp * (kP / KSP);
    const float4* __restrict__ net4 =
        (const float4*)net_out + (size_t)b * kP * (kD / 4) + dc * (DC / 4);
    const float* __restrict__ mkb = mask + (size_t)b * kM * kP;

    const int br0 = tid >> 4;
    const int bc = tid & 15;
    const int ar0 = tid >> 4, ar1 = (tid + 256) >> 4;

    float4 vb0[4], vb1[4], va0[2], va1[2];
    auto LDG = [&](int it, float4* vb, float4* va) {
        const int p0 = pbase + it * KT;
#pragma unroll
        for (int j = 0; j < 4; ++j)
            vb[j] = net4[(size_t)(p0 + br0 + j * 16) * (kD / 4) + bc];
        va[0] = *(const float4*)&mkb[(size_t)ar0 * kP + p0 + bc * 4];
        va[1] = *(const float4*)&mkb[(size_t)ar1 * kP + p0 + bc * 4];
    };
    auto STS = [&](int stage, const float4* vb, const float4* va) {
        float* Bd = smB + stage * (B_STG / 4);
        float* Ad = smA + stage * (A_STG / 4);
#pragma unroll
        for (int j = 0; j < 4; ++j)
            *(float4*)&Bd[(br0 + j * 16) * BST + bc * 4] = vb[j];
        *(float4*)&Ad[ar0 * AST + bc * 4] = va[0];
        *(float4*)&Ad[ar1 * AST + bc * 4] = va[1];
    };

    wmma::fragment<wmma::accumulator, 16, 16, 8, float> acc0, acc1;
    wmma::fill_fragment(acc0, 0.f);
    wmma::fill_fragment(acc1, 0.f);

    LDG(0, vb0, va0);
    LDG(1, vb1, va1);
    STS(0, vb0, va0);
    __syncthreads();

    for (int it = 0; it < NITK; ++it) {
        const int stage = it & 1;
        if (it + 2 < NITK) {
            if (stage == 0) LDG(it + 2, vb0, va0);
            else            LDG(it + 2, vb1, va1);
        }
        if (it + 1 < NITK) {
            if (stage == 0) STS(1, vb1, va1);
            else            STS(0, vb0, va0);
        }

        const float* A = smA + stage * (A_STG / 4);
        const float* B = smB + stage * (B_STG / 4);
#pragma unroll
        for (int ks = 0; ks < 4; ++ks) {
            const int kk = kg * 32 + ks * 8;
            wmma::fragment<wmma::matrix_a, 16, 16, 8, wmma::precision::tf32, wmma::row_major> a0, a1;
            wmma::fragment<wmma::matrix_b, 16, 16, 8, wmma::precision::tf32, wmma::row_major> bf;
            wmma::load_matrix_sync(a0, A + kk, AST);
            wmma::load_matrix_sync(a1, A + 16 * AST + kk, AST);
            wmma::load_matrix_sync(bf, B + kk * BST + nw * 16, BST);
            // A exact {0,1}; B needs RN rounding (see header comment).
#pragma unroll
            for (int i = 0; i < bf.num_elements; ++i)
                bf.x[i] = wmma::__float_to_tf32(bf.x[i]);
            wmma::mma_sync(acc0, a0, bf, acc0);
            wmma::mma_sync(acc1, a1, bf, acc1);
        }
        __syncthreads();
    }

    // Reduce kg halves. Reuse smB as staging: [2][32][64].
    float* so = smB + kg * (kM * DC);
    wmma::store_matrix_sync(so + nw * 16, acc0, DC, wmma::mem_row_major);
    wmma::store_matrix_sync(so + 16 * DC + nw * 16, acc1, DC, wmma::mem_row_major);
    __syncthreads();
#pragma unroll
    for (int j = 0; j < 8; ++j) {
        int idx = tid + j * SEG_THREADS;               // 2048 outputs
        int m = idx >> 6, c = idx & 63;
        float v = smB[idx] + smB[kM * DC + idx];
        g_part[ksp][(size_t)(b * kM + m) * kD + dc * DC + c] = v;
    }
}

// ---------------------------------------------------------------------------
// avg = (part0 + part1) / (npts + 1e-12)
// ---------------------------------------------------------------------------
__global__ void avg_kernel() {
    const int i = blockIdx.x * 256 + threadIdx.x;      // kN*kD exactly
    float v = g_part[0][i] + g_part[1][i];
    g_avg[i] = v / (g_npts[i / kD] + 1e-12f);
}

// ---------------------------------------------------------------------------
// logits = scale * emb @ avg^T  (512x512x768) via tf32 wmma.
// CTA = 32x32 tile, grid 16x16 = 256 CTAs, 128 threads, 4-stage cp.async.
// RN tf32 rounding on both fragments (precision, see segsum note).
// Writes logits AND logits^T (coalesced loss passes).
// ---------------------------------------------------------------------------
constexpr int LK = 32;
__global__ __launch_bounds__(128) void logits_mma(const float* __restrict__ emb,
                                                  const float* __restrict__ lscale) {
    __shared__ __align__(16) float sA[4][32][36];
    __shared__ __align__(16) float sB[4][32][36];
    const int tid = threadIdx.x, w = tid >> 5;
    const int mw = w >> 1, nw = w & 1;
    const int bi = blockIdx.y, bj = blockIdx.x;
    const uint32_t aA = (uint32_t)__cvta_generic_to_shared(&sA[0][0][0]);
    const uint32_t aB = (uint32_t)__cvta_generic_to_shared(&sB[0][0][0]);

    auto ISSUE = [&](int it) {
        int st = it & 3, k0 = it * LK;
#pragma unroll
        for (int j = 0; j < 2; ++j) {           // 256 chunks each matrix
            int e = tid + j * 128;
            int r = e >> 3, c4 = e & 7;
            cpa16(aA + (uint32_t)(st * 32 * 36 + r * 36 + c4 * 4) * 4,
                  emb + (size_t)(bi * 32 + r) * kD + k0 + c4 * 4);
            cpa16(aB + (uint32_t)(st * 32 * 36 + r * 36 + c4 * 4) * 4,
                  g_avg + (size_t)(bj * 32 + r) * kD + k0 + c4 * 4);
        }
        CP_COMMIT();
    };

    wmma::fragment<wmma::accumulator, 16, 16, 8, float> acc;
    wmma::fill_fragment(acc, 0.f);

    ISSUE(0); ISSUE(1); ISSUE(2);
    const int KIT = kD / LK;                    // 24
    for (int it = 0; it < KIT; ++it) {
        int st = it & 3;
        const int rem = KIT - 1 - it;
        if (rem >= 2)      CP_WAIT(2);
        else if (rem == 1) CP_WAIT(1);
        else               CP_WAIT(0);
        __syncthreads();
        if (it + 3 < KIT) ISSUE(it + 3);
#pragma unroll
        for (int ks = 0; ks < 4; ++ks) {
            wmma::fragment<wmma::matrix_a, 16, 16, 8, wmma::precision::tf32, wmma::row_major> af;
            wmma::fragment<wmma::matrix_b, 16, 16, 8, wmma::precision::tf32, wmma::col_major> bf;
            wmma::load_matrix_sync(af, &sA[st][mw * 16][ks * 8], 36);
            wmma::load_matrix_sync(bf, &sB[st][nw * 16][ks * 8], 36);
#pragma unroll
            for (int i = 0; i < af.num_elements; ++i)
                af.x[i] = wmma::__float_to_tf32(af.x[i]);
#pragma unroll
            for (int i = 0; i < bf.num_elements; ++i)
                bf.x[i] = wmma::__float_to_tf32(bf.x[i]);
            wmma::mma_sync(acc, af, bf, acc);
        }
        __syncthreads();
    }

    float* so = &sA[0][0][0];                   // 32 x 36 staging (reuse)
    wmma::store_matrix_sync(so + (mw * 16) * 36 + nw * 16, acc, 36, wmma::mem_row_major);
    __syncthreads();
    const float scale = expf(lscale[0]);
#pragma unroll
    for (int j = 0; j < 2; ++j) {               // logits rows (coalesced)
        int e = tid + j * 128;                  // 256 float4 chunks
        int r = e >> 3, c4 = e & 7;
        float4 v = *(float4*)(so + r * 36 + c4 * 4);
        v.x *= scale; v.y *= scale; v.z *= scale; v.w *= scale;
        *(float4*)&g_logits[(size_t)(bi * 32 + r) * kN + bj * 32 + c4 * 4] = v;
    }
#pragma unroll
    for (int j = 0; j < 2; ++j) {               // logits^T rows (coalesced)
        int e = tid + j * 128;
        int c = e >> 3, i4 = e & 7;             // col of logits, row-quad of i
        float4 v = make_float4(so[(i4 * 4 + 0) * 36 + c] * scale,
                               so[(i4 * 4 + 1) * 36 + c] * scale,
                               so[(i4 * 4 + 2) * 36 + c] * scale,
                               so[(i4 * 4 + 3) * 36 + c] * scale);
        *(float4*)&g_logitsT[(size_t)(bj * 32 + c) * kN + bi * 32 + i4 * 4] = v;
    }
}

// ---------------------------------------------------------------------------
// Loss: blocks 0..511 rows of logits (texts); 512..1023 rows of logits^T (pts).
// ---------------------------------------------------------------------------
__global__ __launch_bounds__(128) void loss_kernel() {
    const int bid = blockIdx.x;
    const int i = bid & (kN - 1);
    const float* __restrict__ row = (bid < kN ? g_logits : g_logitsT) + (size_t)i * kN;
    const int t = threadIdx.x;
    __shared__ float sr[128];

    float rmax = -3.0e38f;
#pragma unroll
    for (int j = t; j < kN; j += 128) rmax = fmaxf(rmax, row[j]);
    sr[t] = rmax;
    __syncthreads();
    for (int w = 64; w > 0; w >>= 1) {
        if (t < w) sr[t] = fmaxf(sr[t], sr[t + w]);
        __syncthreads();
    }
    rmax = sr[0];
    __syncthreads();

    float rs = 0.f;
#pragma unroll
    for (int j = t; j < kN; j += 128) rs += expf(row[j] - rmax);
    sr[t] = rs;
    __syncthreads();
    for (int w = 64; w > 0; w >>= 1) {
        if (t < w) sr[t] += sr[t + w];
        __syncthreads();
    }
    if (t == 0) {
        bool valid = g_npts[i] > 0.f;
        float lse = rmax + logf(sr[0]) - row[i];
        (bid < kN ? g_tloss : g_ploss)[i] = valid ? lse : 0.f;
    }
}

// ---------------------------------------------------------------------------
// Final: nonzero-mean of both loss vectors, averaged.
// ---------------------------------------------------------------------------
__global__ void final_kernel(float* __restrict__ out) {
    const int t = threadIdx.x;   // 512 threads
    __shared__ float s_ts[512], s_tc[512], s_ps[512], s_pc[512];
    float tl = g_tloss[t], pl = g_ploss[t];
    s_ts[t] = (tl > 0.f) ? tl : 0.f;
    s_tc[t] = (tl > 0.f) ? 1.f : 0.f;
    s_ps[t] = (pl > 0.f) ? pl : 0.f;
    s_pc[t] = (pl > 0.f) ? 1.f : 0.f;
    __syncthreads();
    for (int w = 256; w > 0; w >>= 1) {
        if (t < w) {
            s_ts[t] += s_ts[t + w]; s_tc[t] += s_tc[t + w];
            s_ps[t] += s_ps[t + w]; s_pc[t] += s_pc[t + w];
        }
        __syncthreads();
    }
    if (t == 0) {
        float tm = (s_tc[0] > 0.f) ? s_ts[0] / s_tc[0] : 0.f;
        float pm = (s_pc[0] > 0.f) ? s_ps[0] / s_pc[0] : 0.f;
        out[0] = 0.5f * (tm + pm);
    }
}

// ---------------------------------------------------------------------------
// Launch. Inputs: net_out, pt_offset, mask_embs, mask_pts, logit_scale.
// npts + 2 dummies keep segsum as the 4th launch (ncu captures the 4th).
// ---------------------------------------------------------------------------
extern "C" void kernel_launch(void* const* d_in, const int* in_sizes, int n_in,
                              void* d_out, int out_size) {
    (void)in_sizes; (void)n_in; (void)out_size;
    const float* net_out   = (const float*)d_in[0];
    const float* mask_embs = (const float*)d_in[2];
    const float* mask_pts  = (const float*)d_in[3];
    const float* lscale    = (const float*)d_in[4];

    cudaFuncSetAttribute(segsum_mma,
                         cudaFuncAttributeMaxDynamicSharedMemorySize, SEG_SMEM);

    npts_kernel<<<kN, 256>>>(mask_pts);
    dummy_kernel<<<1, 1>>>();
    dummy_kernel<<<1, 1>>>();
    segsum_mma<<<dim3(NDCC, kB, KSP), SEG_THREADS, SEG_SMEM>>>(net_out, mask_pts);
    avg_kernel<<<(kN * kD) / 256, 256>>>();
    logits_mma<<<dim3(16, 16), 128>>>(mask_embs, lscale);
    loss_kernel<<<2 * kN, 128>>>();
    final_kernel<<<1, kN>>>((float*)d_out);
}